// round 4
// baseline (speedup 1.0000x reference)
#include <cuda_runtime.h>

#define NUM_CLASSES 1000
#define FEAT_DIM    256
#define NROWS       262144
#define NBLK        512          // chunks for hierarchical counting sort

// Device-global scratch (no allocation allowed in kernel_launch).
__device__ int g_hist[NBLK * NUM_CLASSES];   // per-block hist -> per-block excl prefix
__device__ int g_count[NUM_CLASSES];
__device__ int g_offset[NUM_CLASSES];
__device__ int g_idx[NROWS];

// ---------------------------------------------------------------------------
// Kernel 1: per-block label histogram (smem privatized, int4 label loads)
// Block b owns rows [b*rpb, (b+1)*rpb); rpb is a multiple of 4.
// ---------------------------------------------------------------------------
__global__ void k_hist(const int* __restrict__ labels, int n, int rpb) {
    __shared__ int h[NUM_CLASSES];
    for (int i = threadIdx.x; i < NUM_CLASSES; i += blockDim.x) h[i] = 0;
    __syncthreads();
    int base = blockIdx.x * rpb;
    int q    = rpb >> 2;
    const int4* lab4 = (const int4*)(labels + base);   // base % 4 == 0
    for (int j4 = threadIdx.x; j4 < q; j4 += blockDim.x) {
        int r = base + (j4 << 2);
        if (r + 3 < n) {
            int4 L = lab4[j4];
            atomicAdd(&h[L.x], 1);
            atomicAdd(&h[L.y], 1);
            atomicAdd(&h[L.z], 1);
            atomicAdd(&h[L.w], 1);
        } else {
            for (int k = 0; k < 4; k++)
                if (r + k < n) atomicAdd(&h[labels[r + k]], 1);
        }
    }
    __syncthreads();
    int* dst = &g_hist[blockIdx.x * NUM_CLASSES];
    for (int i = threadIdx.x; i < NUM_CLASSES; i += blockDim.x) dst[i] = h[i];
}

// ---------------------------------------------------------------------------
// Kernel 2: per-class exclusive scan across the NBLK block-chunks.
// One block per class; NBLK threads. In-place; emits class totals.
// ---------------------------------------------------------------------------
__global__ void k_scanA() {
    int c = blockIdx.x;
    int t = threadIdx.x;
    int v = g_hist[t * NUM_CLASSES + c];

    int lane = t & 31, w = t >> 5;
    int x = v;
    #pragma unroll
    for (int o = 1; o < 32; o <<= 1) {
        int y = __shfl_up_sync(0xffffffffu, x, o);
        if (lane >= o) x += y;
    }
    __shared__ int wt[NBLK / 32];
    if (lane == 31) wt[w] = x;
    __syncthreads();
    if (t == 0) {
        int s = 0;
        #pragma unroll
        for (int i = 0; i < NBLK / 32; i++) { int tmp = wt[i]; wt[i] = s; s += tmp; }
    }
    __syncthreads();
    int incl = x + wt[w];
    g_hist[t * NUM_CLASSES + c] = incl - v;   // exclusive prefix within class
    if (t == NBLK - 1) g_count[c] = incl;     // class total
}

// ---------------------------------------------------------------------------
// Kernel 3: exclusive scan over 1000 class totals (single block)
// ---------------------------------------------------------------------------
__global__ void k_scanB() {
    __shared__ int s[1024];
    int t = threadIdx.x;
    s[t] = (t < NUM_CLASSES) ? g_count[t] : 0;
    for (int off = 1; off < 1024; off <<= 1) {
        __syncthreads();
        int v = (t >= off) ? s[t - off] : 0;
        __syncthreads();
        s[t] += v;
    }
    __syncthreads();
    if (t < NUM_CLASSES) g_offset[t] = (t == 0) ? 0 : s[t - 1];
}

// ---------------------------------------------------------------------------
// Kernel 4: scatter row indices; smem cursors only, int4 label loads.
// With NBLK=512/blockDim=128 each thread owns exactly one int4 chunk —
// minimal dependent chain, 2x block-level parallelism vs round 3.
// ---------------------------------------------------------------------------
__global__ void k_scatter(const int* __restrict__ labels, int n, int rpb) {
    __shared__ int cursor[NUM_CLASSES];
    int b = blockIdx.x;
    const int* pre = &g_hist[b * NUM_CLASSES];
    for (int c = threadIdx.x; c < NUM_CLASSES; c += blockDim.x)
        cursor[c] = g_offset[c] + pre[c];
    __syncthreads();
    int base = b * rpb;
    int q    = rpb >> 2;
    const int4* lab4 = (const int4*)(labels + base);
    for (int j4 = threadIdx.x; j4 < q; j4 += blockDim.x) {
        int r = base + (j4 << 2);
        if (r + 3 < n) {
            int4 L = lab4[j4];
            g_idx[atomicAdd(&cursor[L.x], 1)] = r;
            g_idx[atomicAdd(&cursor[L.y], 1)] = r + 1;
            g_idx[atomicAdd(&cursor[L.z], 1)] = r + 2;
            g_idx[atomicAdd(&cursor[L.w], 1)] = r + 3;
        } else {
            for (int k = 0; k < 4; k++)
                if (r + k < n) {
                    int c = labels[r + k];
                    g_idx[atomicAdd(&cursor[c], 1)] = r + k;
                }
        }
    }
}

// ---------------------------------------------------------------------------
// Kernel 5: per-class segment sum with float4 streaming loads + EMA epilogue.
// 256 threads = 4 row-groups x 64 threads; each group covers a full row with
// 64 LDG.128s. 4 independent accumulators -> 4 loads in flight per thread.
// ---------------------------------------------------------------------------
__global__ void __launch_bounds__(256, 8)
k_reduce(const float4* __restrict__ feats4,
         const float* __restrict__ protos,
         float* __restrict__ out) {
    int c   = blockIdx.x;
    int t   = threadIdx.x;
    int grp = t >> 6;     // 0..3: row group
    int col = t & 63;     // float4 column within the row
    int start = g_offset[c];
    int cnt   = g_count[c];

    __shared__ int sidx[256];
    float4 a0 = make_float4(0.f, 0.f, 0.f, 0.f);
    float4 a1 = make_float4(0.f, 0.f, 0.f, 0.f);
    float4 a2 = make_float4(0.f, 0.f, 0.f, 0.f);
    float4 a3 = make_float4(0.f, 0.f, 0.f, 0.f);

    for (int base = 0; base < cnt; base += 256) {
        int m = min(256, cnt - base);
        if (t < m) sidx[t] = g_idx[start + base + t];
        __syncthreads();
        int j = grp;
        for (; j + 12 < m; j += 16) {
            long r0 = sidx[j];
            long r1 = sidx[j + 4];
            long r2 = sidx[j + 8];
            long r3 = sidx[j + 12];
            float4 v0 = __ldcs(&feats4[r0 * (FEAT_DIM / 4) + col]);
            float4 v1 = __ldcs(&feats4[r1 * (FEAT_DIM / 4) + col]);
            float4 v2 = __ldcs(&feats4[r2 * (FEAT_DIM / 4) + col]);
            float4 v3 = __ldcs(&feats4[r3 * (FEAT_DIM / 4) + col]);
            a0.x += v0.x; a0.y += v0.y; a0.z += v0.z; a0.w += v0.w;
            a1.x += v1.x; a1.y += v1.y; a1.z += v1.z; a1.w += v1.w;
            a2.x += v2.x; a2.y += v2.y; a2.z += v2.z; a2.w += v2.w;
            a3.x += v3.x; a3.y += v3.y; a3.z += v3.z; a3.w += v3.w;
        }
        for (; j < m; j += 4) {
            float4 v = __ldcs(&feats4[(long)sidx[j] * (FEAT_DIM / 4) + col]);
            a0.x += v.x; a0.y += v.y; a0.z += v.z; a0.w += v.w;
        }
        __syncthreads();
    }

    // Combine the 4 per-group partials.
    __shared__ float4 part4[4][64];   // 4 KB
    float4 a = make_float4((a0.x + a1.x) + (a2.x + a3.x),
                           (a0.y + a1.y) + (a2.y + a3.y),
                           (a0.z + a1.z) + (a2.z + a3.z),
                           (a0.w + a1.w) + (a2.w + a3.w));
    part4[grp][col] = a;
    __syncthreads();

    const float* part = (const float*)part4;   // part[g*256 + column]
    float sum = (part[0 * 256 + t] + part[1 * 256 + t])
              + (part[2 * 256 + t] + part[3 * 256 + t]);

    float p = protos[c * FEAT_DIM + t];
    float r = p;
    if (cnt > 0) {
        float mean = sum / (float)cnt;
        r = 0.9f * p + 0.1f * mean;
    }
    out[c * FEAT_DIM + t] = r;
}

// ---------------------------------------------------------------------------
// Launch
// ---------------------------------------------------------------------------
extern "C" void kernel_launch(void* const* d_in, const int* in_sizes, int n_in,
                              void* d_out, int out_size) {
    const float* features   = (const float*)d_in[0];
    const int*   labels     = (const int*)d_in[1];
    const float* prototypes = (const float*)d_in[2];
    float*       out        = (float*)d_out;

    int n = in_sizes[1];
    // rows per block-chunk, multiple of 4 so int4 loads stay aligned
    int rpb = ((n + NBLK * 4 - 1) / (NBLK * 4)) * 4;

    k_hist   <<<NBLK, 128>>>(labels, n, rpb);
    k_scanA  <<<NUM_CLASSES, NBLK>>>();
    k_scanB  <<<1, 1024>>>();
    k_scatter<<<NBLK, 128>>>(labels, n, rpb);
    k_reduce <<<NUM_CLASSES, 256>>>((const float4*)features, prototypes, out);
}

// round 5
// speedup vs baseline: 1.0693x; 1.0693x over previous
#include <cuda_runtime.h>

#define NUM_CLASSES 1000
#define FEAT_DIM    256
#define NROWS       262144
#define NBLK        256          // chunks == blocks of the fused prep kernel
#define LAB_CAP     2048         // smem label cache capacity per block

// Device-global scratch (no allocation allowed in kernel_launch).
__device__ int      g_hist[NBLK * NUM_CLASSES];  // per-block hist -> excl prefix
__device__ int      g_count[NUM_CLASSES];
__device__ int      g_offset[NUM_CLASSES];
__device__ int      g_idx[NROWS];
__device__ unsigned g_bar[4];                    // grid-barrier counters (reset by k_reduce)

// ---------------------------------------------------------------------------
// Software grid barrier. All NBLK blocks are co-resident (grid=256, 256 thr,
// ~12KB smem, low regs -> capacity ~8 blocks/SM on 148 SMs), so spinning is
// deadlock-free. Counters are monotonic within one launch; k_reduce resets
// them afterward (stream-ordered), so graph replays see zeroed counters.
// ---------------------------------------------------------------------------
__device__ __forceinline__ void gridbar(int i) {
    __syncthreads();
    __threadfence();
    if (threadIdx.x == 0) {
        atomicAdd(&g_bar[i], 1u);
        volatile unsigned* p = &g_bar[i];
        while (*p < (unsigned)NBLK) { }
    }
    __syncthreads();
}

// ---------------------------------------------------------------------------
// Fused prep: hist -> per-class scan -> class-offset scan -> scatter.
// Block b owns rows [b*rpb, (b+1)*rpb), rpb multiple of 4.
// ---------------------------------------------------------------------------
__global__ void __launch_bounds__(256)
k_prep(const int* __restrict__ labels, int n, int rpb) {
    __shared__ int h[NUM_CLASSES];      // histogram, reused as scatter cursors
    __shared__ int lab[LAB_CAP];        // label cache for this block's chunk
    __shared__ int wt[8];
    __shared__ int carry;

    int b = blockIdx.x;
    int t = threadIdx.x;
    bool cache = (rpb <= LAB_CAP);

    // ---- Phase 0: histogram + label caching ----
    for (int i = t; i < NUM_CLASSES; i += 256) h[i] = 0;
    __syncthreads();

    int base = b * rpb;
    int q    = rpb >> 2;
    const int4* lab4 = (const int4*)(labels + base);   // base % 4 == 0
    for (int j4 = t; j4 < q; j4 += 256) {
        int r = base + (j4 << 2);
        if (r + 3 < n) {
            int4 L = lab4[j4];
            if (cache) *((int4*)&lab[j4 << 2]) = L;
            atomicAdd(&h[L.x], 1);
            atomicAdd(&h[L.y], 1);
            atomicAdd(&h[L.z], 1);
            atomicAdd(&h[L.w], 1);
        } else {
            for (int k = 0; k < 4; k++) {
                int rr = r + k;
                int c  = (rr < n) ? labels[rr] : -1;
                if (cache) lab[(j4 << 2) + k] = c;
                if (c >= 0) atomicAdd(&h[c], 1);
            }
        }
    }
    __syncthreads();
    for (int i = t; i < NUM_CLASSES; i += 256) g_hist[b * NUM_CLASSES + i] = h[i];

    gridbar(0);

    // ---- Phase 1: per-class exclusive scan across the NBLK chunks ----
    // Blocks 0..249 each own 4 classes; thread t = chunk t.
    if (b < NUM_CLASSES / 4) {
        int lane = t & 31, w = t >> 5;
        #pragma unroll
        for (int k = 0; k < 4; k++) {
            int c = b * 4 + k;
            int v = g_hist[t * NUM_CLASSES + c];
            int x = v;
            #pragma unroll
            for (int o = 1; o < 32; o <<= 1) {
                int y = __shfl_up_sync(0xffffffffu, x, o);
                if (lane >= o) x += y;
            }
            if (lane == 31) wt[w] = x;
            __syncthreads();
            if (t == 0) {
                int s = 0;
                #pragma unroll
                for (int i = 0; i < 8; i++) { int tmp = wt[i]; wt[i] = s; s += tmp; }
            }
            __syncthreads();
            int incl = x + wt[w];
            g_hist[t * NUM_CLASSES + c] = incl - v;     // exclusive prefix
            if (t == NBLK - 1) g_count[c] = incl;       // class total
            __syncthreads();
        }
    }

    gridbar(1);

    // ---- Phase 2: block 0 scans the 1000 class totals -> g_offset ----
    if (b == 0) {
        int lane = t & 31, w = t >> 5;
        if (t == 0) carry = 0;
        __syncthreads();
        for (int rb = 0; rb < 4; rb++) {
            int i = rb * 256 + t;
            int v = (i < NUM_CLASSES) ? g_count[i] : 0;
            int x = v;
            #pragma unroll
            for (int o = 1; o < 32; o <<= 1) {
                int y = __shfl_up_sync(0xffffffffu, x, o);
                if (lane >= o) x += y;
            }
            if (lane == 31) wt[w] = x;
            __syncthreads();
            if (t == 0) {
                int s = 0;
                #pragma unroll
                for (int j = 0; j < 8; j++) { int tmp = wt[j]; wt[j] = s; s += tmp; }
            }
            __syncthreads();
            int incl = x + wt[w];
            int carry_loc = carry;
            if (i < NUM_CLASSES) g_offset[i] = carry_loc + incl - v;
            __syncthreads();
            if (t == 255) carry = carry_loc + incl;
            __syncthreads();
        }
    }

    gridbar(2);

    // ---- Phase 3: scatter (smem cursors, labels from smem cache) ----
    for (int i = t; i < NUM_CLASSES; i += 256)
        h[i] = g_offset[i] + g_hist[b * NUM_CLASSES + i];
    __syncthreads();

    for (int j = t; j < rpb; j += 256) {
        int r = base + j;
        if (r < n) {
            int c = cache ? lab[j] : labels[r];
            if (c >= 0) g_idx[atomicAdd(&h[c], 1)] = r;
        }
    }
}

// ---------------------------------------------------------------------------
// Reduce: per-class segment sum with float4 loads + EMA epilogue (R3 version).
// 256 threads = 4 row-groups x 64 threads; each group covers a full row with
// 64 LDG.128s. Also resets the grid-barrier counters for the next replay.
// ---------------------------------------------------------------------------
__global__ void __launch_bounds__(256, 8)
k_reduce(const float4* __restrict__ feats4,
         const float* __restrict__ protos,
         float* __restrict__ out) {
    if (blockIdx.x == 0 && threadIdx.x < 4) g_bar[threadIdx.x] = 0;

    int c   = blockIdx.x;
    int t   = threadIdx.x;
    int grp = t >> 6;     // 0..3: row group
    int col = t & 63;     // float4 column within the row
    int start = g_offset[c];
    int cnt   = g_count[c];

    __shared__ int sidx[256];
    float4 a0 = make_float4(0.f, 0.f, 0.f, 0.f);
    float4 a1 = make_float4(0.f, 0.f, 0.f, 0.f);

    for (int base = 0; base < cnt; base += 256) {
        int m = min(256, cnt - base);
        if (t < m) sidx[t] = g_idx[start + base + t];
        __syncthreads();
        int j = grp;
        for (; j + 4 < m; j += 8) {
            long r0 = sidx[j];
            long r1 = sidx[j + 4];
            float4 v0 = feats4[r0 * (FEAT_DIM / 4) + col];
            float4 v1 = feats4[r1 * (FEAT_DIM / 4) + col];
            a0.x += v0.x; a0.y += v0.y; a0.z += v0.z; a0.w += v0.w;
            a1.x += v1.x; a1.y += v1.y; a1.z += v1.z; a1.w += v1.w;
        }
        for (; j < m; j += 4) {
            float4 v = feats4[(long)sidx[j] * (FEAT_DIM / 4) + col];
            a0.x += v.x; a0.y += v.y; a0.z += v.z; a0.w += v.w;
        }
        __syncthreads();
    }

    // Combine the 4 per-group partials.
    __shared__ float4 part4[4][64];   // 4 KB
    float4 a = make_float4(a0.x + a1.x, a0.y + a1.y, a0.z + a1.z, a0.w + a1.w);
    part4[grp][col] = a;
    __syncthreads();

    const float* part = (const float*)part4;   // part[g*256 + column]
    float sum = (part[0 * 256 + t] + part[1 * 256 + t])
              + (part[2 * 256 + t] + part[3 * 256 + t]);

    float p = protos[c * FEAT_DIM + t];
    float r = p;
    if (cnt > 0) {
        float mean = sum / (float)cnt;
        r = 0.9f * p + 0.1f * mean;
    }
    out[c * FEAT_DIM + t] = r;
}

// ---------------------------------------------------------------------------
// Launch
// ---------------------------------------------------------------------------
extern "C" void kernel_launch(void* const* d_in, const int* in_sizes, int n_in,
                              void* d_out, int out_size) {
    const float* features   = (const float*)d_in[0];
    const int*   labels     = (const int*)d_in[1];
    const float* prototypes = (const float*)d_in[2];
    float*       out        = (float*)d_out;

    int n = in_sizes[1];
    // rows per block-chunk, multiple of 4 so int4 loads stay aligned
    int rpb = ((n + NBLK * 4 - 1) / (NBLK * 4)) * 4;

    k_prep  <<<NBLK, 256>>>(labels, n, rpb);
    k_reduce<<<NUM_CLASSES, 256>>>((const float4*)features, prototypes, out);
}